// round 10
// baseline (speedup 1.0000x reference)
#include <cuda_runtime.h>
#include <math.h>

#define NPIX (512*512)
#define NB 16
#define SIG 0.125f
#define TAUC 0.125f
#define ALPHA_C 0.15f
#define MU_C 10.0f
#define EPS_C 1e-6f
#define INV1T (1.0f/1.125f)
#define FRLO 0.43000000000029104f
#define FRHI 0.5699999999953434f

// fused PD tiling (shuffle version)
#define TT 44
#define KK 10
#define SS 64
#define PPT 8
#define NTILE 12            // ceil(512/44)

// ---------------- device scratch ----------------
__device__ float g_tmpR[NB*NPIX];
__device__ float g_tmpM[NB*NPIX];
__device__ float g_x  [NB*NPIX];
__device__ float g_Nh [NB*NPIX];
__device__ float g_gm [NB*NPIX];
__device__ float g_Wx [NB*NPIX];   // ALPHA*Wx
__device__ float g_Wy [NB*NPIX];   // ALPHA*Wy
__device__ float g_u [2][NB*NPIX];
__device__ float g_ub[2][NB*NPIX];
__device__ float g_px[2][NB*NPIX];
__device__ float g_py[2][NB*NPIX];

// radix 16 + 16 (histograms in gmem)
__device__ unsigned g_h16x[NB*65536];      // x pass-1 (top 16 bits)
__device__ unsigned g_h16g[NB*65536];      // gm pass-1
__device__ unsigned g_h2x [NB*4*65536];    // x pass-2 (low 16 bits, conditional)
__device__ unsigned g_h2g [NB*2*65536];    // gm pass-2
__device__ unsigned g_pref16x[NB*4];
__device__ unsigned g_rank16x[NB*4];
__device__ unsigned g_pref16g[NB*2];
__device__ unsigned g_rank16g[NB*2];
__device__ float    g_lo[NB];
__device__ float    g_ihl[NB];
__device__ float    g_isig[NB];

__constant__ unsigned c_ranksX[4] = {2621u, 2622u, 259521u, 259522u};
__constant__ unsigned c_ranksG[2] = {131071u, 131072u};

// ---------------- zero all histogram buffers ----------------
__global__ void k_zero_hists() {
    int stride = gridDim.x * blockDim.x;
    int i0 = blockIdx.x * blockDim.x + threadIdx.x;
    for (int i = i0; i < NB*65536; i += stride) { g_h16x[i] = 0; g_h16g[i] = 0; }
    for (int i = i0; i < NB*4*65536; i += stride) g_h2x[i] = 0;
    for (int i = i0; i < NB*2*65536; i += stride) g_h2g[i] = 0;
}

// ---------------- horizontal 31-max-pool ----------------
__global__ void k_hpool(const float* __restrict__ Iy) {
    int row = blockIdx.x, b = blockIdx.y;
    __shared__ float sR[512];
    __shared__ float sM[512];
    int j = threadIdx.x;
    const float* base = Iy + (size_t)b*3*NPIX + (size_t)row*512;
    float r = __ldg(base + j);
    float m = fmaxf(__ldg(base + NPIX + j), __ldg(base + 2*NPIX + j));
    sR[j] = r; sM[j] = m;
    __syncthreads();
    float mr = r, mm = m;
    #pragma unroll
    for (int t = -15; t <= 15; t++) {
        int jj = j + t; jj = jj < 0 ? 0 : (jj > 511 ? 511 : jj);
        mr = fmaxf(mr, sR[jj]);
        mm = fmaxf(mm, sM[jj]);
    }
    size_t o = (size_t)b*NPIX + (size_t)row*512 + j;
    g_tmpR[o] = mr; g_tmpM[o] = mm;
}

// ---------------- vertical 31-max-pool + x + x pass-1 (16-bit, gmem) ----------------
__global__ void k_vpool_x(const float* __restrict__ Iy) {
    int b = blockIdx.z;
    int col0 = blockIdx.x * 32;
    int row0 = blockIdx.y * 64;
    __shared__ float sR[94][32];
    __shared__ float sM[94][32];
    int tid = threadIdx.y * 32 + threadIdx.x;
    for (int idx = tid; idx < 94*32; idx += 256) {
        int rr = idx >> 5, cc = idx & 31;
        int gr = row0 + rr - 15; gr = gr < 0 ? 0 : (gr > 511 ? 511 : gr);
        size_t o = (size_t)b*NPIX + (size_t)gr*512 + col0 + cc;
        sR[rr][cc] = g_tmpR[o];
        sM[rr][cc] = g_tmpM[o];
    }
    __syncthreads();
    int tx = threadIdx.x;
    unsigned* hb = g_h16x + (size_t)b*65536;
    for (int k = 0; k < 8; k++) {
        int r = threadIdx.y * 8 + k;
        float mr = -1e30f, mm = -1e30f;
        #pragma unroll
        for (int t = 0; t < 31; t++) {
            mr = fmaxf(mr, sR[r+t][tx]);
            mm = fmaxf(mm, sM[r+t][tx]);
        }
        int gr = row0 + r;
        size_t o = (size_t)b*NPIX + (size_t)gr*512 + col0 + tx;
        float R = __ldg(Iy + (size_t)b*3*NPIX + (size_t)gr*512 + col0 + tx);
        float xv = fabsf(mr - mm) + R;
        g_x[o] = xv;
        atomicAdd(&hb[__float_as_uint(xv) >> 16], 1u);
    }
}

// ---------------- pass-1 resolve: top-16 bucket per target (grid = NB) ----------------
__global__ void k_res1(int which) {
    int b = blockIdx.x;
    const unsigned* h = (which ? g_h16g : g_h16x) + (size_t)b*65536;
    __shared__ unsigned seg[256];
    __shared__ unsigned cum[257];
    int tid = threadIdx.x;
    unsigned s = 0;
    #pragma unroll 8
    for (int i = 0; i < 256; i++) s += __ldg(&h[tid*256 + i]);
    seg[tid] = s;
    __syncthreads();
    if (tid == 0) {
        unsigned c = 0;
        for (int i = 0; i < 256; i++) { cum[i] = c; c += seg[i]; }
        cum[256] = c;
    }
    __syncthreads();
    int perB = which ? 2 : 4;
    if (tid < perB) {
        unsigned rank = which ? c_ranksG[tid] : c_ranksX[tid];
        int lo = 0, hi = 255;
        while (lo < hi) { int mid = (lo + hi + 1) >> 1; if (cum[mid] <= rank) lo = mid; else hi = mid - 1; }
        unsigned rr = rank - cum[lo];
        unsigned bkt = 255;
        for (int i = 0; i < 256; i++) {
            unsigned c = __ldg(&h[lo*256 + i]);
            if (rr < c) { bkt = (unsigned)i; break; }
            rr -= c;
        }
        unsigned pref = (unsigned)lo*256 + bkt;
        if (which) { g_pref16g[b*2 + tid] = pref; g_rank16g[b*2 + tid] = rr; }
        else       { g_pref16x[b*4 + tid] = pref; g_rank16x[b*4 + tid] = rr; }
    }
}

// ---------------- pass-2 conditional histogram (low 16 bits, gmem) ----------------
__global__ void k_hist2c(int which) {
    int b = blockIdx.y;
    const int perB = which ? 2 : 4;
    const float* src = which ? g_gm : g_x;
    unsigned* gh = which ? g_h2g : g_h2x;
    const unsigned* gp = which ? g_pref16g : g_pref16x;
    unsigned pref[4];
    #pragma unroll
    for (int j = 0; j < 4; j++)
        pref[j] = (j < perB) ? __ldg(&gp[b*perB + j]) : 0xFFFFFFFFu;

    const float4* p = (const float4*)(src + (size_t)b*NPIX);
    for (int i = blockIdx.x * blockDim.x + threadIdx.x; i < NPIX/4; i += gridDim.x * blockDim.x) {
        float4 vv = __ldg(p + i);
        unsigned vs[4] = {__float_as_uint(vv.x), __float_as_uint(vv.y),
                          __float_as_uint(vv.z), __float_as_uint(vv.w)};
        #pragma unroll
        for (int e = 0; e < 4; e++) {
            unsigned v = vs[e];
            unsigned top = v >> 16;
            unsigned bin = v & 0xFFFFu;
            #pragma unroll
            for (int j = 0; j < 4; j++)
                if (j < perB && top == pref[j])
                    atomicAdd(&gh[(size_t)(b*perB + j)*65536 + bin], 1u);
        }
    }
}

// ---------------- pass-2 resolve + finalize lo/ihl or isig (grid = NB) ----------------
__global__ void k_res2(int which) {
    int b = blockIdx.x;
    const int perB = which ? 2 : 4;
    const unsigned* gh = which ? g_h2g : g_h2x;
    const unsigned* gp = which ? g_pref16g : g_pref16x;
    const unsigned* gr = which ? g_rank16g : g_rank16x;
    __shared__ unsigned seg[256];
    __shared__ unsigned cum[257];
    __shared__ float s_sel[4];
    int tid = threadIdx.x;

    for (int tgt = 0; tgt < perB; tgt++) {
        const unsigned* h = gh + (size_t)(b*perB + tgt)*65536;
        unsigned s = 0;
        #pragma unroll 8
        for (int i = 0; i < 256; i++) s += __ldg(&h[tid*256 + i]);
        seg[tid] = s;
        __syncthreads();
        if (tid == 0) {
            unsigned c = 0;
            for (int i = 0; i < 256; i++) { cum[i] = c; c += seg[i]; }
            cum[256] = c;
            unsigned rank = __ldg(&gr[b*perB + tgt]);
            int lo = 0, hi = 255;
            while (lo < hi) { int mid = (lo + hi + 1) >> 1; if (cum[mid] <= rank) lo = mid; else hi = mid - 1; }
            unsigned rr = rank - cum[lo];
            unsigned bkt = 255;
            for (int i = 0; i < 256; i++) {
                unsigned c2 = __ldg(&h[lo*256 + i]);
                if (rr < c2) { bkt = (unsigned)i; break; }
                rr -= c2;
            }
            unsigned low16 = (unsigned)lo*256 + bkt;
            unsigned bits = (__ldg(&gp[b*perB + tgt]) << 16) | low16;
            s_sel[tgt] = __uint_as_float(bits);
        }
        __syncthreads();
    }
    if (tid == 0) {
        if (which == 0) {
            float lo = s_sel[0]*(1.0f-FRLO) + s_sel[1]*FRLO;
            float hi = s_sel[2]*(1.0f-FRHI) + s_sel[3]*FRHI;
            g_lo[b] = lo;
            g_ihl[b] = 1.0f / (hi - lo + EPS_C);
        } else {
            float med = 0.5f * (s_sel[0] + s_sel[1]);
            g_isig[b] = 1.0f / fmaxf(med, EPS_C);
        }
    }
}

// ---------------- N_hat + grad mag + gm pass-1 (16-bit, gmem) ----------------
__global__ void k_nhat() {
    int b = blockIdx.y;
    float lo = __ldg(&g_lo[b]), inv = __ldg(&g_ihl[b]);
    unsigned* hb = g_h16g + (size_t)b*65536;
    size_t base = (size_t)b*NPIX;
    for (int idx = blockIdx.x * blockDim.x + threadIdx.x; idx < NPIX; idx += 64*256) {
        int i = idx >> 9, j = idx & 511;
        size_t o = base + idx;
        float xc = __ldg(&g_x[o]);
        float n00 = fminf(fmaxf((xc - lo) * inv, 0.0f), 1.0f);
        float dx = 0.0f, dy = 0.0f;
        if (j < 511) {
            float xr = __ldg(&g_x[o + 1]);
            dx = fminf(fmaxf((xr - lo) * inv, 0.0f), 1.0f) - n00;
        }
        if (i < 511) {
            float xd = __ldg(&g_x[o + 512]);
            dy = fminf(fmaxf((xd - lo) * inv, 0.0f), 1.0f) - n00;
        }
        float gm = sqrtf(dx*dx + dy*dy + EPS_C);
        g_Nh[o] = n00;
        g_gm[o] = gm;
        atomicAdd(&hb[__float_as_uint(gm) >> 16], 1u);
    }
}

// ---------------- bounds alpha*Wx, alpha*Wy ----------------
__global__ void k_wxy() {
    int b = blockIdx.y;
    float isig = __ldg(&g_isig[b]);
    size_t base = (size_t)b*NPIX;
    for (int idx = blockIdx.x * blockDim.x + threadIdx.x; idx < NPIX; idx += 64*256) {
        int i = idx >> 9, j = idx & 511;
        size_t o = base + idx;
        float n00 = __ldg(&g_Nh[o]);
        float dx = (j < 511) ? (__ldg(&g_Nh[o + 1]) - n00) : 0.0f;
        float dy = (i < 511) ? (__ldg(&g_Nh[o + 512]) - n00) : 0.0f;
        g_Wx[o] = ALPHA_C * (1.0f + MU_C * __expf(-fabsf(dx) * isig));
        g_Wy[o] = ALPHA_C * (1.0f + MU_C * __expf(-fabsf(dy) * isig));
    }
}

// ---------------- shuffle-register fused PD (unchanged from R7) ----------------
template<bool FIRST, bool LAST>
__global__ void __launch_bounds__(512, 2) k_pdshfl(int rd, int wr, float* __restrict__ out) {
    extern __shared__ float sm[];
    float* s_bx     = sm;
    float* s_by     = sm + SS*SS;
    float* s_tnh    = sm + 2*SS*SS;
    float* s_rowub  = sm + 3*SS*SS;          // [9][SS]
    float* s_rowpy  = s_rowub + 9*SS;        // [9][SS]
    float* s_seamub = s_rowpy + 9*SS;        // [SS]
    float* s_seampx = s_seamub + SS;         // [SS]

    int b = blockIdx.z;
    int rx0 = blockIdx.x * TT - KK;
    int ry0 = blockIdx.y * TT - KK;
    size_t base = (size_t)b * NPIX;
    int tx = threadIdx.x, ty = threadIdx.y;
    int R0 = ty * PPT;
    int gj = rx0 + tx;
    int gi0 = ry0 + R0;
    bool jok = (gj >= 0) && (gj < 512);

    float ru[PPT], rub[PPT], rpx[PPT], rpy[PPT];

    #pragma unroll
    for (int k = 0; k < PPT; k++) {
        int gi = gi0 + k;
        int o = (R0 + k)*SS + tx;
        if (jok && gi >= 0 && gi < 512) {
            size_t go = base + (size_t)gi*512 + gj;
            float nh = __ldg(&g_Nh[go]);
            s_tnh[o] = TAUC * nh;
            s_bx[o]  = __ldg(&g_Wx[go]);
            s_by[o]  = __ldg(&g_Wy[go]);
            if (FIRST) {
                ru[k] = nh; rub[k] = nh; rpx[k] = 0.0f; rpy[k] = 0.0f;
            } else {
                ru[k]  = __ldg(&g_u [rd][go]);
                rub[k] = __ldg(&g_ub[rd][go]);
                rpx[k] = __ldg(&g_px[rd][go]);
                rpy[k] = __ldg(&g_py[rd][go]);
            }
        } else {
            s_tnh[o] = 0.0f; s_bx[o] = 0.0f; s_by[o] = 0.0f;
            ru[k] = 0.0f; rub[k] = 0.0f; rpx[k] = 0.0f; rpy[k] = 0.0f;
        }
    }
    s_rowub[ty*SS + tx] = rub[0];
    if (ty == 0) { s_rowub[8*SS + tx] = 0.0f; s_rowpy[0*SS + tx] = 0.0f; }
    if (tx == 32) {
        #pragma unroll
        for (int k = 0; k < PPT; k++) s_seamub[R0 + k] = rub[k];
    }
    __syncthreads();

    const unsigned FULL = 0xffffffffu;
    bool jlt511 = (gj < 511);
    bool jgt0   = (gj > 0);

    for (int t = 0; t < KK; t++) {
        float ubbelow = s_rowub[(ty+1)*SS + tx];
        #pragma unroll
        for (int k = 0; k < PPT; k++) {
            float ubc = rub[k];
            float ubr = __shfl_down_sync(FULL, ubc, 1);
            if (tx == 31) ubr = s_seamub[R0 + k];
            float ubd = (k < PPT-1) ? rub[k+1] : ubbelow;
            int gi = gi0 + k;
            float dx = jlt511     ? (ubr - ubc) : 0.0f;
            float dy = (gi < 511) ? (ubd - ubc) : 0.0f;
            int o = (R0 + k)*SS + tx;
            float bx = s_bx[o], by = s_by[o];
            rpx[k] = fminf(fmaxf(rpx[k] + SIG*dx, -bx), bx);
            rpy[k] = fminf(fmaxf(rpy[k] + SIG*dy, -by), by);
        }
        s_rowpy[(ty+1)*SS + tx] = rpy[PPT-1];
        if (tx == 31) {
            #pragma unroll
            for (int k = 0; k < PPT; k++) s_seampx[R0 + k] = rpx[k];
        }
        __syncthreads();

        float pyabove = s_rowpy[ty*SS + tx];
        #pragma unroll
        for (int k = 0; k < PPT; k++) {
            float pxc = rpx[k];
            float pxl = __shfl_up_sync(FULL, pxc, 1);
            if (tx == 32) pxl = s_seampx[R0 + k];
            if (!jgt0) pxl = 0.0f;
            float pyu = (k > 0) ? rpy[k-1] : pyabove;
            int gi = gi0 + k;
            if (gi <= 0) pyu = 0.0f;
            int o = (R0 + k)*SS + tx;
            float uc = ru[k];
            float un = (uc + TAUC*(rpx[k] - pxl + rpy[k] - pyu) + s_tnh[o]) * INV1T;
            rub[k] = 2.0f*un - uc;
            ru[k] = un;
        }
        s_rowub[ty*SS + tx] = rub[0];
        if (tx == 32) {
            #pragma unroll
            for (int k = 0; k < PPT; k++) s_seamub[R0 + k] = rub[k];
        }
        __syncthreads();
    }

    if (tx >= KK && tx < KK+TT && gj < 512) {
        #pragma unroll
        for (int k = 0; k < PPT; k++) {
            int r = R0 + k;
            if (r >= KK && r < KK+TT) {
                int gi = gi0 + k;
                if (gi < 512) {
                    size_t go = base + (size_t)gi*512 + gj;
                    if (LAST) {
                        out[go] = fminf(fmaxf(ru[k], 0.0f), 1.0f);
                    } else {
                        g_u [wr][go] = ru[k];
                        g_ub[wr][go] = rub[k];
                        g_px[wr][go] = rpx[k];
                        g_py[wr][go] = rpy[k];
                    }
                }
            }
        }
    }
}

// ---------------- launch (single stream, no device allocations) ----------------
extern "C" void kernel_launch(void* const* d_in, const int* in_sizes, int n_in,
                              void* d_out, int out_size) {
    const float* Iy = (const float*)d_in[0];
    float* out = (float*)d_out;

    const int smbytes = (3*SS*SS + 2*9*SS + 2*SS) * (int)sizeof(float);
    cudaFuncSetAttribute(k_pdshfl<true,false>,  cudaFuncAttributeMaxDynamicSharedMemorySize, smbytes);
    cudaFuncSetAttribute(k_pdshfl<false,false>, cudaFuncAttributeMaxDynamicSharedMemorySize, smbytes);
    cudaFuncSetAttribute(k_pdshfl<false,true>,  cudaFuncAttributeMaxDynamicSharedMemorySize, smbytes);

    dim3 b32x8(32, 8);

    k_zero_hists<<<512, 256>>>();
    k_hpool  <<<dim3(512, NB), 512>>>(Iy);
    k_vpool_x<<<dim3(16, 8, NB), b32x8>>>(Iy);      // + x pass-1 (16-bit, gmem)

    // x quantiles: resolve-1, conditional pass-2, resolve-2 (writes lo/ihl)
    k_res1<<<NB, 256>>>(0);
    k_hist2c<<<dim3(32, NB), 256>>>(0);
    k_res2<<<NB, 256>>>(0);

    k_nhat<<<dim3(64, NB), 256>>>();                // + gm pass-1 (16-bit, gmem)

    // gm quantiles
    k_res1<<<NB, 256>>>(1);
    k_hist2c<<<dim3(32, NB), 256>>>(1);
    k_res2<<<NB, 256>>>(1);

    k_wxy<<<dim3(64, NB), 256>>>();

    // 30 PD iterations = 3 fused launches of 10
    dim3 bTile(SS, 8);
    dim3 gTile(NTILE, NTILE, NB);
    k_pdshfl<true,  false><<<gTile, bTile, smbytes>>>(0, 0, nullptr);
    k_pdshfl<false, false><<<gTile, bTile, smbytes>>>(0, 1, nullptr);
    k_pdshfl<false, true ><<<gTile, bTile, smbytes>>>(1, 0, out);
}

// round 11
// speedup vs baseline: 1.4727x; 1.4727x over previous
#include <cuda_runtime.h>
#include <math.h>

#define NPIX (512*512)
#define NB 16
#define SIG 0.125f
#define TAUC 0.125f
#define ALPHA_C 0.15f
#define MU_C 10.0f
#define EPS_C 1e-6f
#define INV1T (1.0f/1.125f)
#define FRLO 0.43000000000029104f
#define FRHI 0.5699999999953434f

// fused PD tiling (shuffle version)
#define TT 44
#define KK 10
#define SS 64
#define PPT 8
#define NTILE 12            // ceil(512/44)

// ---------------- device scratch ----------------
__device__ float g_tmpR[NB*NPIX];
__device__ float g_tmpM[NB*NPIX];
__device__ float g_x  [NB*NPIX];
__device__ float g_Nh [NB*NPIX];
__device__ float g_gm [NB*NPIX];
__device__ float g_Wx [NB*NPIX];   // ALPHA*Wx
__device__ float g_Wy [NB*NPIX];   // ALPHA*Wy
__device__ float g_u [2][NB*NPIX];
__device__ float g_ub[2][NB*NPIX];
__device__ float g_px[2][NB*NPIX];
__device__ float g_py[2][NB*NPIX];

// radix 8+8+8+8 (R7 scheme — final)
__device__ unsigned g_hist1 [NB*256];      // x pass-1
__device__ unsigned g_hist1g[NB*256];      // gm pass-1
__device__ unsigned g_histX[3][64*256];    // x passes 2..4
__device__ unsigned g_histG[3][32*256];    // gm passes 2..4

__constant__ int c_ranksX[4] = {2621, 2622, 259521, 259522};
__constant__ int c_ranksG[2] = {131071, 131072};

// ---------------- zero all histogram buffers ----------------
__global__ void k_zero_hists() {
    unsigned* hx = &g_histX[0][0];
    unsigned* hg = &g_histG[0][0];
    for (int i = blockIdx.x * blockDim.x + threadIdx.x; i < 81920; i += gridDim.x * blockDim.x) {
        if (i < 4096) g_hist1[i] = 0;
        else if (i < 8192) g_hist1g[i - 4096] = 0;
        else if (i < 8192 + 49152) hx[i - 8192] = 0;
        else hg[i - 57344] = 0;
    }
}

// ---------------- warp-collective radix resolve (256-bin) ----------------
__device__ __forceinline__ unsigned warp_resolve_step(const unsigned* hist, unsigned& rank, int lane) {
    unsigned c[8]; unsigned s = 0;
    #pragma unroll
    for (int i = 0; i < 8; i++) { c[i] = __ldg(&hist[lane*8 + i]); s += c[i]; }
    unsigned pre = s;
    #pragma unroll
    for (int d = 1; d < 32; d <<= 1) {
        unsigned v = __shfl_up_sync(0xffffffffu, pre, d);
        if (lane >= d) pre += v;
    }
    unsigned excl = pre - s;
    bool hit = (rank >= excl) && (rank < excl + s);
    unsigned m = __ballot_sync(0xffffffffu, hit);
    int hl = m ? (__ffs(m) - 1) : 31;
    unsigned bkt = 255, rr = 0;
    if (lane == hl) {
        if (m) {
            rr = rank - excl;
            int i = 0;
            while (i < 7 && rr >= c[i]) { rr -= c[i]; i++; }
            bkt = (unsigned)(hl*8 + i);
        } else { bkt = 255; rr = 0; }
    }
    bkt = __shfl_sync(0xffffffffu, bkt, hl);
    rr  = __shfl_sync(0xffffffffu, rr,  hl);
    rank = rr;
    return bkt;
}

__device__ __forceinline__ unsigned chain_prefix(int which, int b, int tgt, int upto, int lane) {
    unsigned rank = which ? (unsigned)c_ranksG[tgt] : (unsigned)c_ranksX[tgt];
    unsigned prefix = 0u;
    for (int pass = 1; pass <= upto; pass++) {
        const unsigned* hist;
        if (pass == 1) hist = (which ? g_hist1g : g_hist1) + b*256;
        else {
            int perB = which ? 2 : 4;
            hist = (which ? &g_histG[pass-2][0] : &g_histX[pass-2][0]) + (b*perB + tgt)*256;
        }
        unsigned bkt = warp_resolve_step(hist, rank, lane);
        prefix |= bkt << (8*(4-pass));
    }
    return prefix;
}

// ---------------- horizontal 31-max-pool ----------------
__global__ void k_hpool(const float* __restrict__ Iy) {
    int row = blockIdx.x, b = blockIdx.y;
    __shared__ float sR[512];
    __shared__ float sM[512];
    int j = threadIdx.x;
    const float* base = Iy + (size_t)b*3*NPIX + (size_t)row*512;
    float r = __ldg(base + j);
    float m = fmaxf(__ldg(base + NPIX + j), __ldg(base + 2*NPIX + j));
    sR[j] = r; sM[j] = m;
    __syncthreads();
    float mr = r, mm = m;
    #pragma unroll
    for (int t = -15; t <= 15; t++) {
        int jj = j + t; jj = jj < 0 ? 0 : (jj > 511 ? 511 : jj);
        mr = fmaxf(mr, sR[jj]);
        mm = fmaxf(mm, sM[jj]);
    }
    size_t o = (size_t)b*NPIX + (size_t)row*512 + j;
    g_tmpR[o] = mr; g_tmpM[o] = mm;
}

// ---------------- vertical 31-max-pool + x + x pass-1 histogram ----------------
__global__ void k_vpool_x(const float* __restrict__ Iy) {
    int b = blockIdx.z;
    int col0 = blockIdx.x * 32;
    int row0 = blockIdx.y * 64;
    __shared__ float sR[94][32];
    __shared__ float sM[94][32];
    __shared__ unsigned h[8*256];
    int tid = threadIdx.y * 32 + threadIdx.x;
    for (int i = tid; i < 8*256; i += 256) h[i] = 0;
    for (int idx = tid; idx < 94*32; idx += 256) {
        int rr = idx >> 5, cc = idx & 31;
        int gr = row0 + rr - 15; gr = gr < 0 ? 0 : (gr > 511 ? 511 : gr);
        size_t o = (size_t)b*NPIX + (size_t)gr*512 + col0 + cc;
        sR[rr][cc] = g_tmpR[o];
        sM[rr][cc] = g_tmpM[o];
    }
    __syncthreads();
    int tx = threadIdx.x;
    unsigned rep = (tid & 7) * 256;
    for (int k = 0; k < 8; k++) {
        int r = threadIdx.y * 8 + k;
        float mr = -1e30f, mm = -1e30f;
        #pragma unroll
        for (int t = 0; t < 31; t++) {
            mr = fmaxf(mr, sR[r+t][tx]);
            mm = fmaxf(mm, sM[r+t][tx]);
        }
        int gr = row0 + r;
        size_t o = (size_t)b*NPIX + (size_t)gr*512 + col0 + tx;
        float R = __ldg(Iy + (size_t)b*3*NPIX + (size_t)gr*512 + col0 + tx);
        float xv = fabsf(mr - mm) + R;
        g_x[o] = xv;
        atomicAdd(&h[rep + (__float_as_uint(xv) >> 24)], 1u);
    }
    __syncthreads();
    for (int i = tid; i < 256; i += 256) {
        unsigned s = 0;
        #pragma unroll
        for (int r = 0; r < 8; r++) s += h[r*256 + i];
        if (s) atomicAdd(&g_hist1[b*256 + i], s);
    }
}

// ---------------- conditional histogram; prefix chain prologue; dedup ----------------
__global__ void k_histT(int which, int pass) {
    int b = blockIdx.y;
    const int perB = which ? 2 : 4;
    const float* src = which ? g_gm : g_x;
    unsigned* gh = which ? &g_histG[pass-2][0] : &g_histX[pass-2][0];
    int shift = 8 * (4 - pass);
    unsigned mask = 0xFFFFFFFFu << (shift + 8);

    __shared__ unsigned s_pref[4];
    __shared__ int s_slot[4];
    __shared__ int s_nu;
    __shared__ unsigned h[2][4*256];
    int warp = threadIdx.x >> 5, lane = threadIdx.x & 31;
    for (int i = threadIdx.x; i < 2*4*256; i += blockDim.x) (&h[0][0])[i] = 0;
    if (warp < perB) {
        unsigned p = chain_prefix(which, b, warp, pass - 1, lane);
        if (lane == 0) s_pref[warp] = p & mask;
    }
    __syncthreads();
    if (threadIdx.x == 0) {
        unsigned up[4]; int nu = 0;
        for (int j = 0; j < perB; j++) {
            int k = 0;
            while (k < nu && up[k] != s_pref[j]) k++;
            if (k == nu) up[nu++] = s_pref[j];
            s_slot[j] = k;
        }
        for (int k = 0; k < nu; k++) s_pref[k] = up[k];
        s_nu = nu;
    }
    __syncthreads();
    const int nu = s_nu;
    unsigned p0 = s_pref[0];
    unsigned p1 = (nu > 1) ? s_pref[1] : 0xFFFFFFF1u;
    unsigned p2 = (nu > 2) ? s_pref[2] : 0xFFFFFFF2u;
    unsigned p3 = (nu > 3) ? s_pref[3] : 0xFFFFFFF3u;

    unsigned rep = threadIdx.x & 1;
    const float4* p = (const float4*)(src + (size_t)b*NPIX);
    for (int i = blockIdx.x * blockDim.x + threadIdx.x; i < NPIX/4; i += gridDim.x * blockDim.x) {
        float4 vv = __ldg(p + i);
        unsigned vs[4] = {__float_as_uint(vv.x), __float_as_uint(vv.y),
                          __float_as_uint(vv.z), __float_as_uint(vv.w)};
        #pragma unroll
        for (int e = 0; e < 4; e++) {
            unsigned v = vs[e];
            unsigned vm = v & mask;
            unsigned bin = (v >> shift) & 0xFFu;
            if      (vm == p0) atomicAdd(&h[rep][bin], 1u);
            else if (vm == p1) atomicAdd(&h[rep][256 + bin], 1u);
            else if (vm == p2) atomicAdd(&h[rep][2*256 + bin], 1u);
            else if (vm == p3) atomicAdd(&h[rep][3*256 + bin], 1u);
        }
    }
    __syncthreads();
    for (int i = threadIdx.x; i < perB*256; i += blockDim.x) {
        int tgt = i >> 8, bin = i & 255;
        int sl = s_slot[tgt];
        unsigned s = h[0][sl*256 + bin] + h[1][sl*256 + bin];
        if (s) atomicAdd(&gh[(b*perB + tgt)*256 + bin], s);
    }
}

// ---------------- N_hat + grad mag + gm pass-1 histogram; x-resolve prologue ----------------
__global__ void k_nhat() {
    int b = blockIdx.y;
    __shared__ unsigned h[8*256];
    __shared__ float s_sel[4];
    int warp = threadIdx.x >> 5, lane = threadIdx.x & 31;
    for (int i = threadIdx.x; i < 8*256; i += blockDim.x) h[i] = 0;
    if (warp < 4) {
        unsigned p = chain_prefix(0, b, warp, 4, lane);
        if (lane == 0) s_sel[warp] = __uint_as_float(p);
    }
    __syncthreads();
    float lo = s_sel[0]*(1.0f-FRLO) + s_sel[1]*FRLO;
    float hi = s_sel[2]*(1.0f-FRHI) + s_sel[3]*FRHI;
    float inv = 1.0f / (hi - lo + EPS_C);

    unsigned rep = (threadIdx.x & 7) * 256;
    size_t base = (size_t)b*NPIX;
    for (int idx = blockIdx.x * blockDim.x + threadIdx.x; idx < NPIX; idx += 64*256) {
        int i = idx >> 9, j = idx & 511;
        size_t o = base + idx;
        float xc = __ldg(&g_x[o]);
        float n00 = fminf(fmaxf((xc - lo) * inv, 0.0f), 1.0f);
        float dx = 0.0f, dy = 0.0f;
        if (j < 511) {
            float xr = __ldg(&g_x[o + 1]);
            dx = fminf(fmaxf((xr - lo) * inv, 0.0f), 1.0f) - n00;
        }
        if (i < 511) {
            float xd = __ldg(&g_x[o + 512]);
            dy = fminf(fmaxf((xd - lo) * inv, 0.0f), 1.0f) - n00;
        }
        float gm = sqrtf(dx*dx + dy*dy + EPS_C);
        g_Nh[o] = n00;
        g_gm[o] = gm;
        atomicAdd(&h[rep + (__float_as_uint(gm) >> 24)], 1u);
    }
    __syncthreads();
    for (int i = threadIdx.x; i < 256; i += blockDim.x) {
        unsigned s = 0;
        #pragma unroll
        for (int r = 0; r < 8; r++) s += h[r*256 + i];
        if (s) atomicAdd(&g_hist1g[b*256 + i], s);
    }
}

// ---------------- bounds; gm-resolve prologue ----------------
__global__ void k_wxy() {
    int b = blockIdx.y;
    __shared__ float s_sel[2];
    int warp = threadIdx.x >> 5, lane = threadIdx.x & 31;
    if (warp < 2) {
        unsigned p = chain_prefix(1, b, warp, 4, lane);
        if (lane == 0) s_sel[warp] = __uint_as_float(p);
    }
    __syncthreads();
    float med = 0.5f * (s_sel[0] + s_sel[1]);
    float isig = 1.0f / fmaxf(med, EPS_C);

    size_t base = (size_t)b*NPIX;
    for (int idx = blockIdx.x * blockDim.x + threadIdx.x; idx < NPIX; idx += 64*256) {
        int i = idx >> 9, j = idx & 511;
        size_t o = base + idx;
        float n00 = __ldg(&g_Nh[o]);
        float dx = (j < 511) ? (__ldg(&g_Nh[o + 1]) - n00) : 0.0f;
        float dy = (i < 511) ? (__ldg(&g_Nh[o + 512]) - n00) : 0.0f;
        g_Wx[o] = ALPHA_C * (1.0f + MU_C * __expf(-fabsf(dx) * isig));
        g_Wy[o] = ALPHA_C * (1.0f + MU_C * __expf(-fabsf(dy) * isig));
    }
}

// ---------------- shuffle-register fused PD + shrinking row-rect ----------------
// Row guards are warp-uniform (block (64,8): all lanes share r = ty*8+k).
// Out-of-rect rows keep stale registers/smem; the R4 cone proof shows those
// values never reach the stored interior -> bit-identical output.
template<bool FIRST, bool LAST>
__global__ void __launch_bounds__(512, 2) k_pdshfl(int rd, int wr, float* __restrict__ out) {
    extern __shared__ float sm[];
    float* s_bx     = sm;
    float* s_by     = sm + SS*SS;
    float* s_tnh    = sm + 2*SS*SS;
    float* s_rowub  = sm + 3*SS*SS;          // [9][SS]
    float* s_rowpy  = s_rowub + 9*SS;        // [9][SS]
    float* s_seamub = s_rowpy + 9*SS;        // [SS]
    float* s_seampx = s_seamub + SS;         // [SS]

    int b = blockIdx.z;
    int rx0 = blockIdx.x * TT - KK;
    int ry0 = blockIdx.y * TT - KK;
    size_t base = (size_t)b * NPIX;
    int tx = threadIdx.x, ty = threadIdx.y;
    int R0 = ty * PPT;
    int gj = rx0 + tx;
    int gi0 = ry0 + R0;
    bool jok = (gj >= 0) && (gj < 512);

    float ru[PPT], rub[PPT], rpx[PPT], rpy[PPT];

    #pragma unroll
    for (int k = 0; k < PPT; k++) {
        int gi = gi0 + k;
        int o = (R0 + k)*SS + tx;
        if (jok && gi >= 0 && gi < 512) {
            size_t go = base + (size_t)gi*512 + gj;
            float nh = __ldg(&g_Nh[go]);
            s_tnh[o] = TAUC * nh;
            s_bx[o]  = __ldg(&g_Wx[go]);
            s_by[o]  = __ldg(&g_Wy[go]);
            if (FIRST) {
                ru[k] = nh; rub[k] = nh; rpx[k] = 0.0f; rpy[k] = 0.0f;
            } else {
                ru[k]  = __ldg(&g_u [rd][go]);
                rub[k] = __ldg(&g_ub[rd][go]);
                rpx[k] = __ldg(&g_px[rd][go]);
                rpy[k] = __ldg(&g_py[rd][go]);
            }
        } else {
            s_tnh[o] = 0.0f; s_bx[o] = 0.0f; s_by[o] = 0.0f;
            ru[k] = 0.0f; rub[k] = 0.0f; rpx[k] = 0.0f; rpy[k] = 0.0f;
        }
    }
    s_rowub[ty*SS + tx] = rub[0];
    if (ty == 0) { s_rowub[8*SS + tx] = 0.0f; s_rowpy[0*SS + tx] = 0.0f; }
    if (tx == 32) {
        #pragma unroll
        for (int k = 0; k < PPT; k++) s_seamub[R0 + k] = rub[k];
    }
    __syncthreads();

    const unsigned FULL = 0xffffffffu;
    bool jlt511 = (gj < 511);
    bool jgt0   = (gj > 0);

    // valid row range, pinned at true image edges
    int rA = (ry0 < 0) ? -ry0 : 0;
    int rB = (511 - ry0 < SS-1) ? (511 - ry0) : (SS-1);

    for (int t = 0; t < KK; t++) {
        // ---- dual over rows [rA, rB] ----
        float ubbelow = s_rowub[(ty+1)*SS + tx];
        #pragma unroll
        for (int k = 0; k < PPT; k++) {
            int r = R0 + k;
            if (r >= rA && r <= rB) {
                float ubc = rub[k];
                float ubr = __shfl_down_sync(FULL, ubc, 1);
                if (tx == 31) ubr = s_seamub[r];
                float ubd = (k < PPT-1) ? rub[k+1] : ubbelow;
                int gi = gi0 + k;
                float dx = jlt511     ? (ubr - ubc) : 0.0f;
                float dy = (gi < 511) ? (ubd - ubc) : 0.0f;
                int o = r*SS + tx;
                float bx = s_bx[o], by = s_by[o];
                rpx[k] = fminf(fmaxf(rpx[k] + SIG*dx, -bx), bx);
                rpy[k] = fminf(fmaxf(rpy[k] + SIG*dy, -by), by);
            }
        }
        s_rowpy[(ty+1)*SS + tx] = rpy[PPT-1];
        if (tx == 31) {
            #pragma unroll
            for (int k = 0; k < PPT; k++) s_seampx[R0 + k] = rpx[k];
        }
        __syncthreads();

        int rA2 = rA + ((ry0 + rA) != 0);
        int rB2 = rB - ((ry0 + rB) != 511);

        // ---- primal over rows [rA2, rB2] ----
        float pyabove = s_rowpy[ty*SS + tx];
        #pragma unroll
        for (int k = 0; k < PPT; k++) {
            int r = R0 + k;
            if (r >= rA2 && r <= rB2) {
                float pxc = rpx[k];
                float pxl = __shfl_up_sync(FULL, pxc, 1);
                if (tx == 32) pxl = s_seampx[r];
                if (!jgt0) pxl = 0.0f;
                float pyu = (k > 0) ? rpy[k-1] : pyabove;
                int gi = gi0 + k;
                if (gi <= 0) pyu = 0.0f;
                int o = r*SS + tx;
                float uc = ru[k];
                float un = (uc + TAUC*(rpx[k] - pxl + rpy[k] - pyu) + s_tnh[o]) * INV1T;
                rub[k] = 2.0f*un - uc;
                ru[k] = un;
            }
        }
        s_rowub[ty*SS + tx] = rub[0];
        if (tx == 32) {
            #pragma unroll
            for (int k = 0; k < PPT; k++) s_seamub[R0 + k] = rub[k];
        }
        __syncthreads();
        rA = rA2; rB = rB2;
    }

    if (tx >= KK && tx < KK+TT && gj < 512) {
        #pragma unroll
        for (int k = 0; k < PPT; k++) {
            int r = R0 + k;
            if (r >= KK && r < KK+TT) {
                int gi = gi0 + k;
                if (gi < 512) {
                    size_t go = base + (size_t)gi*512 + gj;
                    if (LAST) {
                        out[go] = fminf(fmaxf(ru[k], 0.0f), 1.0f);
                    } else {
                        g_u [wr][go] = ru[k];
                        g_ub[wr][go] = rub[k];
                        g_px[wr][go] = rpx[k];
                        g_py[wr][go] = rpy[k];
                    }
                }
            }
        }
    }
}

// ---------------- launch (single stream, no device allocations) ----------------
extern "C" void kernel_launch(void* const* d_in, const int* in_sizes, int n_in,
                              void* d_out, int out_size) {
    const float* Iy = (const float*)d_in[0];
    float* out = (float*)d_out;

    const int smbytes = (3*SS*SS + 2*9*SS + 2*SS) * (int)sizeof(float);
    cudaFuncSetAttribute(k_pdshfl<true,false>,  cudaFuncAttributeMaxDynamicSharedMemorySize, smbytes);
    cudaFuncSetAttribute(k_pdshfl<false,false>, cudaFuncAttributeMaxDynamicSharedMemorySize, smbytes);
    cudaFuncSetAttribute(k_pdshfl<false,true>,  cudaFuncAttributeMaxDynamicSharedMemorySize, smbytes);

    dim3 b32x8(32, 8);

    k_zero_hists<<<64, 256>>>();
    k_hpool  <<<dim3(512, NB), 512>>>(Iy);
    k_vpool_x<<<dim3(16, 8, NB), b32x8>>>(Iy);   // + x pass-1 histogram

    // x quantiles (resolve chains run inside consumers)
    k_histT<<<dim3(64, NB), 256>>>(0, 2);
    k_histT<<<dim3(64, NB), 256>>>(0, 3);
    k_histT<<<dim3(64, NB), 256>>>(0, 4);

    k_nhat<<<dim3(64, NB), 256>>>();             // x-resolve prologue + gm pass-1

    // gm quantiles
    k_histT<<<dim3(64, NB), 256>>>(1, 2);
    k_histT<<<dim3(64, NB), 256>>>(1, 3);
    k_histT<<<dim3(64, NB), 256>>>(1, 4);

    k_wxy<<<dim3(64, NB), 256>>>();              // gm-resolve prologue

    // 30 PD iterations = 3 fused launches of 10
    dim3 bTile(SS, 8);
    dim3 gTile(NTILE, NTILE, NB);
    k_pdshfl<true,  false><<<gTile, bTile, smbytes>>>(0, 0, nullptr);
    k_pdshfl<false, false><<<gTile, bTile, smbytes>>>(0, 1, nullptr);
    k_pdshfl<false, true ><<<gTile, bTile, smbytes>>>(1, 0, out);
}

// round 12
// speedup vs baseline: 1.7091x; 1.1606x over previous
#include <cuda_runtime.h>
#include <math.h>

#define NPIX (512*512)
#define NB 16
#define SIG 0.125f
#define TAUC 0.125f
#define ALPHA_C 0.15f
#define MU_C 10.0f
#define EPS_C 1e-6f
#define INV1T (1.0f/1.125f)
#define FRLO 0.43000000000029104f
#define FRHI 0.5699999999953434f

// fused PD tiling (shuffle version, frozen since R7)
#define TT 44
#define KK 10
#define SS 64
#define PPT 8
#define NTILE 12            // ceil(512/44)

#define CAP 32768           // candidate buffer per target

// ---------------- device scratch ----------------
__device__ float g_tmpR[NB*NPIX];
__device__ float g_tmpM[NB*NPIX];
__device__ float g_x  [NB*NPIX];
__device__ float g_Nh [NB*NPIX];
__device__ float g_gm [NB*NPIX];
__device__ float g_Wx [NB*NPIX];   // ALPHA*Wx
__device__ float g_Wy [NB*NPIX];   // ALPHA*Wy
__device__ float g_u [2][NB*NPIX];
__device__ float g_ub[2][NB*NPIX];
__device__ float g_px[2][NB*NPIX];
__device__ float g_py[2][NB*NPIX];

// radix: pass1 (8 bits) + pass2 (8 bits) + candidate collection (low 16 bits)
__device__ unsigned g_hist1 [NB*256];      // x pass-1
__device__ unsigned g_hist1g[NB*256];      // gm pass-1
__device__ unsigned g_hX2[NB*4*256];       // x pass-2
__device__ unsigned g_hG2[NB*2*256];       // gm pass-2
__device__ unsigned g_cnt [NB*6];          // per (b, slot) candidate counts; slots 0-3=x, 4-5=gm
__device__ unsigned g_cand[(size_t)NB*6*CAP];
__device__ float    g_lo[NB];
__device__ float    g_ihl[NB];
__device__ float    g_isig[NB];

__constant__ int c_ranksX[4] = {2621, 2622, 259521, 259522};
__constant__ int c_ranksG[2] = {131071, 131072};

// ---------------- zero histogram buffers + counters ----------------
__global__ void k_zero_hists() {
    int stride = gridDim.x * blockDim.x;
    int i0 = blockIdx.x * blockDim.x + threadIdx.x;
    for (int i = i0; i < NB*256; i += stride) { g_hist1[i] = 0; g_hist1g[i] = 0; }
    for (int i = i0; i < NB*4*256; i += stride) g_hX2[i] = 0;
    for (int i = i0; i < NB*2*256; i += stride) g_hG2[i] = 0;
    if (i0 < NB*6) g_cnt[i0] = 0;
}

// ---------------- warp-collective 256-bin resolve (global-mem hist) ----------------
__device__ __forceinline__ unsigned wrs256(const unsigned* hist, unsigned& rank, int lane) {
    unsigned c[8]; unsigned s = 0;
    #pragma unroll
    for (int i = 0; i < 8; i++) { c[i] = __ldg(&hist[lane*8 + i]); s += c[i]; }
    unsigned pre = s;
    #pragma unroll
    for (int d = 1; d < 32; d <<= 1) {
        unsigned v = __shfl_up_sync(0xffffffffu, pre, d);
        if (lane >= d) pre += v;
    }
    unsigned excl = pre - s;
    bool hit = (rank >= excl) && (rank < excl + s);
    unsigned m = __ballot_sync(0xffffffffu, hit);
    int hl = m ? (__ffs(m) - 1) : 31;
    unsigned bkt = 255, rr = 0;
    if (lane == hl) {
        if (m) {
            rr = rank - excl;
            int i = 0;
            while (i < 7 && rr >= c[i]) { rr -= c[i]; i++; }
            bkt = (unsigned)(hl*8 + i);
        } else { bkt = 255; rr = 0; }
    }
    bkt = __shfl_sync(0xffffffffu, bkt, hl);
    rr  = __shfl_sync(0xffffffffu, rr,  hl);
    rank = rr;
    return bkt;
}

// same, but for a shared-memory histogram (no __ldg)
__device__ __forceinline__ unsigned wrs256_sm(const unsigned* hist, unsigned& rank, int lane) {
    unsigned c[8]; unsigned s = 0;
    #pragma unroll
    for (int i = 0; i < 8; i++) { c[i] = hist[lane*8 + i]; s += c[i]; }
    unsigned pre = s;
    #pragma unroll
    for (int d = 1; d < 32; d <<= 1) {
        unsigned v = __shfl_up_sync(0xffffffffu, pre, d);
        if (lane >= d) pre += v;
    }
    unsigned excl = pre - s;
    bool hit = (rank >= excl) && (rank < excl + s);
    unsigned m = __ballot_sync(0xffffffffu, hit);
    int hl = m ? (__ffs(m) - 1) : 31;
    unsigned bkt = 255, rr = 0;
    if (lane == hl) {
        if (m) {
            rr = rank - excl;
            int i = 0;
            while (i < 7 && rr >= c[i]) { rr -= c[i]; i++; }
            bkt = (unsigned)(hl*8 + i);
        } else { bkt = 255; rr = 0; }
    }
    bkt = __shfl_sync(0xffffffffu, bkt, hl);
    rr  = __shfl_sync(0xffffffffu, rr,  hl);
    rank = rr;
    return bkt;
}

// resolve pass 1 only: returns 8-bit bucket, updates rank
__device__ __forceinline__ unsigned res_p1(int which, int b, int tgt, int lane, unsigned& rank) {
    rank = which ? (unsigned)c_ranksG[tgt] : (unsigned)c_ranksX[tgt];
    const unsigned* h1 = (which ? g_hist1g : g_hist1) + b*256;
    return wrs256(h1, rank, lane);
}

// resolve passes 1+2: returns 16-bit prefix (in bits [31:16]), rank within bucket
__device__ __forceinline__ unsigned res_p12(int which, int b, int tgt, int lane, unsigned& rank) {
    unsigned p1 = res_p1(which, b, tgt, lane, rank);
    int perB = which ? 2 : 4;
    const unsigned* h2 = (which ? g_hG2 : g_hX2) + (b*perB + tgt)*256;
    unsigned p2 = wrs256(h2, rank, lane);
    return (p1 << 24) | (p2 << 16);
}

// ---------------- horizontal 31-max-pool ----------------
__global__ void k_hpool(const float* __restrict__ Iy) {
    int row = blockIdx.x, b = blockIdx.y;
    __shared__ float sR[512];
    __shared__ float sM[512];
    int j = threadIdx.x;
    const float* base = Iy + (size_t)b*3*NPIX + (size_t)row*512;
    float r = __ldg(base + j);
    float m = fmaxf(__ldg(base + NPIX + j), __ldg(base + 2*NPIX + j));
    sR[j] = r; sM[j] = m;
    __syncthreads();
    float mr = r, mm = m;
    #pragma unroll
    for (int t = -15; t <= 15; t++) {
        int jj = j + t; jj = jj < 0 ? 0 : (jj > 511 ? 511 : jj);
        mr = fmaxf(mr, sR[jj]);
        mm = fmaxf(mm, sM[jj]);
    }
    size_t o = (size_t)b*NPIX + (size_t)row*512 + j;
    g_tmpR[o] = mr; g_tmpM[o] = mm;
}

// ---------------- vertical 31-max-pool + x + x pass-1 histogram ----------------
__global__ void k_vpool_x(const float* __restrict__ Iy) {
    int b = blockIdx.z;
    int col0 = blockIdx.x * 32;
    int row0 = blockIdx.y * 64;
    __shared__ float sR[94][32];
    __shared__ float sM[94][32];
    __shared__ unsigned h[8*256];
    int tid = threadIdx.y * 32 + threadIdx.x;
    for (int i = tid; i < 8*256; i += 256) h[i] = 0;
    for (int idx = tid; idx < 94*32; idx += 256) {
        int rr = idx >> 5, cc = idx & 31;
        int gr = row0 + rr - 15; gr = gr < 0 ? 0 : (gr > 511 ? 511 : gr);
        size_t o = (size_t)b*NPIX + (size_t)gr*512 + col0 + cc;
        sR[rr][cc] = g_tmpR[o];
        sM[rr][cc] = g_tmpM[o];
    }
    __syncthreads();
    int tx = threadIdx.x;
    unsigned rep = (tid & 7) * 256;
    for (int k = 0; k < 8; k++) {
        int r = threadIdx.y * 8 + k;
        float mr = -1e30f, mm = -1e30f;
        #pragma unroll
        for (int t = 0; t < 31; t++) {
            mr = fmaxf(mr, sR[r+t][tx]);
            mm = fmaxf(mm, sM[r+t][tx]);
        }
        int gr = row0 + r;
        size_t o = (size_t)b*NPIX + (size_t)gr*512 + col0 + tx;
        float R = __ldg(Iy + (size_t)b*3*NPIX + (size_t)gr*512 + col0 + tx);
        float xv = fabsf(mr - mm) + R;
        g_x[o] = xv;
        atomicAdd(&h[rep + (__float_as_uint(xv) >> 24)], 1u);
    }
    __syncthreads();
    for (int i = tid; i < 256; i += 256) {
        unsigned s = 0;
        #pragma unroll
        for (int r = 0; r < 8; r++) s += h[r*256 + i];
        if (s) atomicAdd(&g_hist1[b*256 + i], s);
    }
}

// ---------------- pass-2 conditional histogram (R7 structure) ----------------
__global__ void k_hist2(int which) {
    int b = blockIdx.y;
    const int perB = which ? 2 : 4;
    const float* src = which ? g_gm : g_x;
    unsigned* gh = which ? g_hG2 : g_hX2;

    __shared__ unsigned s_pref[4];
    __shared__ unsigned h[2][4*256];
    int warp = threadIdx.x >> 5, lane = threadIdx.x & 31;
    for (int i = threadIdx.x; i < 2*4*256; i += blockDim.x) (&h[0][0])[i] = 0;
    if (warp < perB) {
        unsigned rank;
        unsigned p1 = res_p1(which, b, warp, lane, rank);
        if (lane == 0) s_pref[warp] = p1;
    }
    __syncthreads();
    unsigned pref[4];
    #pragma unroll
    for (int j = 0; j < 4; j++) pref[j] = (j < perB) ? s_pref[j] : 0xFFFFFFFFu;

    unsigned rep = threadIdx.x & 1;
    const float4* p = (const float4*)(src + (size_t)b*NPIX);
    for (int i = blockIdx.x * blockDim.x + threadIdx.x; i < NPIX/4; i += gridDim.x * blockDim.x) {
        float4 vv = __ldg(p + i);
        unsigned vs[4] = {__float_as_uint(vv.x), __float_as_uint(vv.y),
                          __float_as_uint(vv.z), __float_as_uint(vv.w)};
        #pragma unroll
        for (int e = 0; e < 4; e++) {
            unsigned v = vs[e];
            unsigned top = v >> 24;
            unsigned bin = (v >> 16) & 0xFFu;
            #pragma unroll
            for (int j = 0; j < 4; j++)
                if (j < perB && top == pref[j]) atomicAdd(&h[rep][j*256 + bin], 1u);
        }
    }
    __syncthreads();
    for (int i = threadIdx.x; i < perB*256; i += blockDim.x) {
        unsigned s = h[0][i] + h[1][i];
        if (s) atomicAdd(&gh[(b*perB + (i >> 8))*256 + (i & 255)], s);
    }
}

// ---------------- candidate collection: values matching any target's 16-bit prefix ----------------
__global__ void k_collect(int which) {
    int b = blockIdx.y;
    const int perB = which ? 2 : 4;
    const float* src = which ? g_gm : g_x;
    int sbase = b*6 + (which ? 4 : 0);

    __shared__ unsigned s_pref[4];
    int warp = threadIdx.x >> 5, lane = threadIdx.x & 31;
    if (warp < perB) {
        unsigned rank;
        unsigned p = res_p12(which, b, warp, lane, rank);
        if (lane == 0) s_pref[warp] = p >> 16;     // 16-bit key
    }
    __syncthreads();
    unsigned pref[4];
    #pragma unroll
    for (int j = 0; j < 4; j++) pref[j] = (j < perB) ? s_pref[j] : 0xFFFFFFFFu;

    const float4* p = (const float4*)(src + (size_t)b*NPIX);
    for (int i = blockIdx.x * blockDim.x + threadIdx.x; i < NPIX/4; i += gridDim.x * blockDim.x) {
        float4 vv = __ldg(p + i);
        unsigned vs[4] = {__float_as_uint(vv.x), __float_as_uint(vv.y),
                          __float_as_uint(vv.z), __float_as_uint(vv.w)};
        #pragma unroll
        for (int e = 0; e < 4; e++) {
            unsigned v = vs[e];
            unsigned top = v >> 16;
            #pragma unroll
            for (int j = 0; j < 4; j++) {
                if (j < perB && top == pref[j]) {
                    unsigned pos = atomicAdd(&g_cnt[sbase + j], 1u);
                    if (pos < CAP) g_cand[(size_t)(sbase + j)*CAP + pos] = v;
                }
            }
        }
    }
}

// ---------------- select: exact low-16-bit radix over collected candidates ----------------
// grid = NB. Order-invariant counting selection -> deterministic, bit-identical
// to the old pass-3/4 radix.
__global__ void k_select(int which) {
    int b = blockIdx.x;
    const int perB = which ? 2 : 4;
    int sbase = b*6 + (which ? 4 : 0);
    __shared__ unsigned hist[256];
    __shared__ unsigned s_p, s_r, s_b3;
    __shared__ float s_sel[4];
    int tid = threadIdx.x;
    int lane = tid & 31;

    for (int tgt = 0; tgt < perB; tgt++) {
        if (tid < 32) {
            unsigned rank;
            unsigned p = res_p12(which, b, tgt, lane, rank);
            if (lane == 0) { s_p = p; s_r = rank; }
        }
        hist[tid] = 0;
        __syncthreads();
        unsigned n = g_cnt[sbase + tgt]; if (n > CAP) n = CAP;
        const unsigned* cand = g_cand + (size_t)(sbase + tgt)*CAP;
        // pass 3: bits [15:8]
        for (unsigned i = tid; i < n; i += 256)
            atomicAdd(&hist[(__ldg(&cand[i]) >> 8) & 0xFFu], 1u);
        __syncthreads();
        if (tid < 32) {
            unsigned r = s_r;
            unsigned b3 = wrs256_sm(hist, r, lane);
            if (lane == 0) { s_b3 = b3; s_r = r; }
        }
        __syncthreads();
        unsigned b3 = s_b3;
        hist[tid] = 0;
        __syncthreads();
        // pass 4: bits [7:0] among candidates with byte3 == b3
        for (unsigned i = tid; i < n; i += 256) {
            unsigned v = __ldg(&cand[i]);
            if (((v >> 8) & 0xFFu) == b3) atomicAdd(&hist[v & 0xFFu], 1u);
        }
        __syncthreads();
        if (tid < 32) {
            unsigned r = s_r;
            unsigned b4 = wrs256_sm(hist, r, lane);
            if (lane == 0) s_sel[tgt] = __uint_as_float(s_p | (b3 << 8) | b4);
        }
        __syncthreads();
    }
    if (tid == 0) {
        if (which == 0) {
            float lo = s_sel[0]*(1.0f-FRLO) + s_sel[1]*FRLO;
            float hi = s_sel[2]*(1.0f-FRHI) + s_sel[3]*FRHI;
            g_lo[b] = lo;
            g_ihl[b] = 1.0f / (hi - lo + EPS_C);
        } else {
            float med = 0.5f * (s_sel[0] + s_sel[1]);
            g_isig[b] = 1.0f / fmaxf(med, EPS_C);
        }
    }
}

// ---------------- N_hat + grad mag + gm pass-1 histogram ----------------
__global__ void k_nhat() {
    int b = blockIdx.y;
    __shared__ unsigned h[8*256];
    for (int i = threadIdx.x; i < 8*256; i += blockDim.x) h[i] = 0;
    __syncthreads();
    float lo = __ldg(&g_lo[b]), inv = __ldg(&g_ihl[b]);
    unsigned rep = (threadIdx.x & 7) * 256;
    size_t base = (size_t)b*NPIX;
    for (int idx = blockIdx.x * blockDim.x + threadIdx.x; idx < NPIX; idx += 64*256) {
        int i = idx >> 9, j = idx & 511;
        size_t o = base + idx;
        float xc = __ldg(&g_x[o]);
        float n00 = fminf(fmaxf((xc - lo) * inv, 0.0f), 1.0f);
        float dx = 0.0f, dy = 0.0f;
        if (j < 511) {
            float xr = __ldg(&g_x[o + 1]);
            dx = fminf(fmaxf((xr - lo) * inv, 0.0f), 1.0f) - n00;
        }
        if (i < 511) {
            float xd = __ldg(&g_x[o + 512]);
            dy = fminf(fmaxf((xd - lo) * inv, 0.0f), 1.0f) - n00;
        }
        float gm = sqrtf(dx*dx + dy*dy + EPS_C);
        g_Nh[o] = n00;
        g_gm[o] = gm;
        atomicAdd(&h[rep + (__float_as_uint(gm) >> 24)], 1u);
    }
    __syncthreads();
    for (int i = threadIdx.x; i < 256; i += blockDim.x) {
        unsigned s = 0;
        #pragma unroll
        for (int r = 0; r < 8; r++) s += h[r*256 + i];
        if (s) atomicAdd(&g_hist1g[b*256 + i], s);
    }
}

// ---------------- bounds alpha*Wx, alpha*Wy ----------------
__global__ void k_wxy() {
    int b = blockIdx.y;
    float isig = __ldg(&g_isig[b]);
    size_t base = (size_t)b*NPIX;
    for (int idx = blockIdx.x * blockDim.x + threadIdx.x; idx < NPIX; idx += 64*256) {
        int i = idx >> 9, j = idx & 511;
        size_t o = base + idx;
        float n00 = __ldg(&g_Nh[o]);
        float dx = (j < 511) ? (__ldg(&g_Nh[o + 1]) - n00) : 0.0f;
        float dy = (i < 511) ? (__ldg(&g_Nh[o + 512]) - n00) : 0.0f;
        g_Wx[o] = ALPHA_C * (1.0f + MU_C * __expf(-fabsf(dx) * isig));
        g_Wy[o] = ALPHA_C * (1.0f + MU_C * __expf(-fabsf(dy) * isig));
    }
}

// ---------------- shuffle-register fused PD (FROZEN: exact R7 body) ----------------
template<bool FIRST, bool LAST>
__global__ void __launch_bounds__(512, 2) k_pdshfl(int rd, int wr, float* __restrict__ out) {
    extern __shared__ float sm[];
    float* s_bx     = sm;
    float* s_by     = sm + SS*SS;
    float* s_tnh    = sm + 2*SS*SS;
    float* s_rowub  = sm + 3*SS*SS;          // [9][SS]
    float* s_rowpy  = s_rowub + 9*SS;        // [9][SS]
    float* s_seamub = s_rowpy + 9*SS;        // [SS]
    float* s_seampx = s_seamub + SS;         // [SS]

    int b = blockIdx.z;
    int rx0 = blockIdx.x * TT - KK;
    int ry0 = blockIdx.y * TT - KK;
    size_t base = (size_t)b * NPIX;
    int tx = threadIdx.x, ty = threadIdx.y;
    int R0 = ty * PPT;
    int gj = rx0 + tx;
    int gi0 = ry0 + R0;
    bool jok = (gj >= 0) && (gj < 512);

    float ru[PPT], rub[PPT], rpx[PPT], rpy[PPT];

    #pragma unroll
    for (int k = 0; k < PPT; k++) {
        int gi = gi0 + k;
        int o = (R0 + k)*SS + tx;
        if (jok && gi >= 0 && gi < 512) {
            size_t go = base + (size_t)gi*512 + gj;
            float nh = __ldg(&g_Nh[go]);
            s_tnh[o] = TAUC * nh;
            s_bx[o]  = __ldg(&g_Wx[go]);
            s_by[o]  = __ldg(&g_Wy[go]);
            if (FIRST) {
                ru[k] = nh; rub[k] = nh; rpx[k] = 0.0f; rpy[k] = 0.0f;
            } else {
                ru[k]  = __ldg(&g_u [rd][go]);
                rub[k] = __ldg(&g_ub[rd][go]);
                rpx[k] = __ldg(&g_px[rd][go]);
                rpy[k] = __ldg(&g_py[rd][go]);
            }
        } else {
            s_tnh[o] = 0.0f; s_bx[o] = 0.0f; s_by[o] = 0.0f;
            ru[k] = 0.0f; rub[k] = 0.0f; rpx[k] = 0.0f; rpy[k] = 0.0f;
        }
    }
    s_rowub[ty*SS + tx] = rub[0];
    if (ty == 0) { s_rowub[8*SS + tx] = 0.0f; s_rowpy[0*SS + tx] = 0.0f; }
    if (tx == 32) {
        #pragma unroll
        for (int k = 0; k < PPT; k++) s_seamub[R0 + k] = rub[k];
    }
    __syncthreads();

    const unsigned FULL = 0xffffffffu;
    bool jlt511 = (gj < 511);
    bool jgt0   = (gj > 0);

    for (int t = 0; t < KK; t++) {
        float ubbelow = s_rowub[(ty+1)*SS + tx];
        #pragma unroll
        for (int k = 0; k < PPT; k++) {
            float ubc = rub[k];
            float ubr = __shfl_down_sync(FULL, ubc, 1);
            if (tx == 31) ubr = s_seamub[R0 + k];
            float ubd = (k < PPT-1) ? rub[k+1] : ubbelow;
            int gi = gi0 + k;
            float dx = jlt511     ? (ubr - ubc) : 0.0f;
            float dy = (gi < 511) ? (ubd - ubc) : 0.0f;
            int o = (R0 + k)*SS + tx;
            float bx = s_bx[o], by = s_by[o];
            rpx[k] = fminf(fmaxf(rpx[k] + SIG*dx, -bx), bx);
            rpy[k] = fminf(fmaxf(rpy[k] + SIG*dy, -by), by);
        }
        s_rowpy[(ty+1)*SS + tx] = rpy[PPT-1];
        if (tx == 31) {
            #pragma unroll
            for (int k = 0; k < PPT; k++) s_seampx[R0 + k] = rpx[k];
        }
        __syncthreads();

        float pyabove = s_rowpy[ty*SS + tx];
        #pragma unroll
        for (int k = 0; k < PPT; k++) {
            float pxc = rpx[k];
            float pxl = __shfl_up_sync(FULL, pxc, 1);
            if (tx == 32) pxl = s_seampx[R0 + k];
            if (!jgt0) pxl = 0.0f;
            float pyu = (k > 0) ? rpy[k-1] : pyabove;
            int gi = gi0 + k;
            if (gi <= 0) pyu = 0.0f;
            int o = (R0 + k)*SS + tx;
            float uc = ru[k];
            float un = (uc + TAUC*(rpx[k] - pxl + rpy[k] - pyu) + s_tnh[o]) * INV1T;
            rub[k] = 2.0f*un - uc;
            ru[k] = un;
        }
        s_rowub[ty*SS + tx] = rub[0];
        if (tx == 32) {
            #pragma unroll
            for (int k = 0; k < PPT; k++) s_seamub[R0 + k] = rub[k];
        }
        __syncthreads();
    }

    if (tx >= KK && tx < KK+TT && gj < 512) {
        #pragma unroll
        for (int k = 0; k < PPT; k++) {
            int r = R0 + k;
            if (r >= KK && r < KK+TT) {
                int gi = gi0 + k;
                if (gi < 512) {
                    size_t go = base + (size_t)gi*512 + gj;
                    if (LAST) {
                        out[go] = fminf(fmaxf(ru[k], 0.0f), 1.0f);
                    } else {
                        g_u [wr][go] = ru[k];
                        g_ub[wr][go] = rub[k];
                        g_px[wr][go] = rpx[k];
                        g_py[wr][go] = rpy[k];
                    }
                }
            }
        }
    }
}

// ---------------- launch (single stream, no device allocations) ----------------
extern "C" void kernel_launch(void* const* d_in, const int* in_sizes, int n_in,
                              void* d_out, int out_size) {
    const float* Iy = (const float*)d_in[0];
    float* out = (float*)d_out;

    const int smbytes = (3*SS*SS + 2*9*SS + 2*SS) * (int)sizeof(float);
    cudaFuncSetAttribute(k_pdshfl<true,false>,  cudaFuncAttributeMaxDynamicSharedMemorySize, smbytes);
    cudaFuncSetAttribute(k_pdshfl<false,false>, cudaFuncAttributeMaxDynamicSharedMemorySize, smbytes);
    cudaFuncSetAttribute(k_pdshfl<false,true>,  cudaFuncAttributeMaxDynamicSharedMemorySize, smbytes);

    dim3 b32x8(32, 8);

    k_zero_hists<<<64, 256>>>();
    k_hpool  <<<dim3(512, NB), 512>>>(Iy);
    k_vpool_x<<<dim3(16, 8, NB), b32x8>>>(Iy);   // + x pass-1 histogram

    // x quantiles: pass-2 scan, candidate collect, exact select -> g_lo/g_ihl
    k_hist2  <<<dim3(32, NB), 256>>>(0);
    k_collect<<<dim3(32, NB), 256>>>(0);
    k_select <<<NB, 256>>>(0);

    k_nhat<<<dim3(64, NB), 256>>>();             // + gm pass-1 histogram

    // gm quantiles -> g_isig
    k_hist2  <<<dim3(32, NB), 256>>>(1);
    k_collect<<<dim3(32, NB), 256>>>(1);
    k_select <<<NB, 256>>>(1);

    k_wxy<<<dim3(64, NB), 256>>>();

    // 30 PD iterations = 3 fused launches of 10 (frozen R7 config)
    dim3 bTile(SS, 8);
    dim3 gTile(NTILE, NTILE, NB);
    k_pdshfl<true,  false><<<gTile, bTile, smbytes>>>(0, 0, nullptr);
    k_pdshfl<false, false><<<gTile, bTile, smbytes>>>(0, 1, nullptr);
    k_pdshfl<false, true ><<<gTile, bTile, smbytes>>>(1, 0, out);
}